// round 9
// baseline (speedup 1.0000x reference)
#include <cuda_runtime.h>
#include <cuda_bf16.h>
#include <math.h>

#define L 4096
#define E 300
#define H 512
#define G 2048   // 4*H
#define TT 24
#define XW 1024  // 2*H

#define RB 64      // blocks per LSTM direction (8 hidden units each)
#define RTH 256    // threads per LSTM block (8 warps)
#define NGRP 8     // arrival groups per step (8 blocks per group = 64-unit h chunk)
#define GSTRIDE 64 // ints between group counters (256B apart)
#define STEP_INTS (NGRP * GSTRIDE)   // 512 ints per step

// ------------------------ scratch (no allocs allowed) ------------------------
__device__ float g_pre0f[(size_t)L * G];
__device__ float g_pre0b[(size_t)L * G];
__device__ float g_pre1f[(size_t)L * G];
__device__ float g_pre1b[(size_t)L * G];
__device__ float g_x1[(size_t)L * XW];
__device__ float g_x2[(size_t)L * XW];
__device__ float g_emis[(size_t)L * TT];
__device__ int   g_bar[(size_t)2 * 2 * L * STEP_INTS];  // [layer][dir][step][group]

// ------------------------ helpers ------------------------
__device__ __forceinline__ float warp_sum(float v) {
#pragma unroll
    for (int o = 16; o > 0; o >>= 1) v += __shfl_down_sync(0xffffffffu, v, o);
    return v;
}
__device__ __forceinline__ float warp_max_all(float v) {
#pragma unroll
    for (int o = 16; o > 0; o >>= 1) v = fmaxf(v, __shfl_xor_sync(0xffffffffu, v, o));
    return v;
}
__device__ __forceinline__ float sigmoid_fast(float x) {
    return __fdividef(1.0f, 1.0f + __expf(-x));
}
__device__ __forceinline__ float tanh_fast(float x) {
    // tanh(x) = 1 - 2/(exp(2x)+1); saturates correctly for |x| large
    return 1.0f - __fdividef(2.0f, __expf(2.0f * x) + 1.0f);
}
__device__ __forceinline__ float sigmoidf_(float x) { return 1.0f / (1.0f + __expf(-x)); }

// ------------------------ dual GEMM: C[M,N] = A[M,K] @ B[N,K]^T + bias[N] ------------------------
__global__ __launch_bounds__(256) void gemm_bias2_kernel(
    const float* __restrict__ A, const int* __restrict__ rowmap,
    const float* __restrict__ B0, const float* __restrict__ bias0, float* __restrict__ C0,
    const float* __restrict__ B1, const float* __restrict__ bias1, float* __restrict__ C1,
    int M, int N, int K)
{
    const float* B    = blockIdx.z ? B1    : B0;
    const float* bias = blockIdx.z ? bias1 : bias0;
    float*       C    = blockIdx.z ? C1    : C0;

    __shared__ float As[8][128];
    __shared__ float Bs[8][128];

    int tid = threadIdx.x;
    int bm = blockIdx.y, bn = blockIdx.x;
    int tx = tid & 15, ty = tid >> 4;

    int loadRow = tid >> 1;            // 0..127
    int loadCol = (tid & 1) * 4;       // 0 or 4

    int aRowG = bm * 128 + loadRow;
    int aPhys = rowmap ? rowmap[aRowG] : aRowG;
    const float* Aptr = A + (size_t)aPhys * K;
    const float* Bptr = B + (size_t)(bn * 128 + loadRow) * K;

    float acc[8][8];
#pragma unroll
    for (int i = 0; i < 8; i++)
#pragma unroll
        for (int j = 0; j < 8; j++) acc[i][j] = 0.0f;

    for (int k0 = 0; k0 < K; k0 += 8) {
        int k = k0 + loadCol;
        if (k + 3 < K) {
            float4 va = *(const float4*)(Aptr + k);
            As[loadCol + 0][loadRow] = va.x;
            As[loadCol + 1][loadRow] = va.y;
            As[loadCol + 2][loadRow] = va.z;
            As[loadCol + 3][loadRow] = va.w;
            float4 vb = *(const float4*)(Bptr + k);
            Bs[loadCol + 0][loadRow] = vb.x;
            Bs[loadCol + 1][loadRow] = vb.y;
            Bs[loadCol + 2][loadRow] = vb.z;
            Bs[loadCol + 3][loadRow] = vb.w;
        } else {
#pragma unroll
            for (int i = 0; i < 4; i++) {
                int kk = k + i;
                As[loadCol + i][loadRow] = (kk < K) ? Aptr[kk] : 0.0f;
                Bs[loadCol + i][loadRow] = (kk < K) ? Bptr[kk] : 0.0f;
            }
        }
        __syncthreads();
#pragma unroll
        for (int kk = 0; kk < 8; kk++) {
            float a[8], b[8];
#pragma unroll
            for (int i = 0; i < 8; i++) a[i] = As[kk][ty * 8 + i];
#pragma unroll
            for (int j = 0; j < 8; j++) b[j] = Bs[kk][tx * 8 + j];
#pragma unroll
            for (int i = 0; i < 8; i++)
#pragma unroll
                for (int j = 0; j < 8; j++) acc[i][j] += a[i] * b[j];
        }
        __syncthreads();
    }

#pragma unroll
    for (int i = 0; i < 8; i++) {
        int row = bm * 128 + ty * 8 + i;
#pragma unroll
        for (int j = 0; j < 8; j++) {
            int col = bn * 128 + tx * 8 + j;
            C[(size_t)row * N + col] = acc[i][j] + bias[col];
        }
    }
}

// ------------------------ persistent bidirectional LSTM layer ------------------------
// 2*RB blocks; [0,RB)=fwd, [RB,2RB)=bwd. Block owns 8 units (32 gate rows, 4/warp).
// ARRIVAL-DRIVEN CHUNKED MATVEC: h is consumed in 8 chunks of 64, each gated on its
// own group counter (group g = blocks 8g..8g+7 = units 64g..64g+63). One parallel
// probe (lanes 0-7, acquire) -> ballot; ready chunks folded immediately (wave 1);
// missing chunks spun on individually (wave 2) so laggard wait overlaps compute.
// ONE __syncthreads per step (gates parity-double-buffered; pre prefetched into
// per-warp registers). Warp 7 does all 32 nonlinearities in parallel (fast tanh),
// c-update on lanes 0-7, publishes via __syncwarp + atom.release.gpu.
__global__ __launch_bounds__(RTH) void lstm_kernel(
    const float* __restrict__ pre_f, const float* __restrict__ pre_b,
    const float* __restrict__ whh_f, const float* __restrict__ whh_b,
    float* __restrict__ out, int* __restrict__ bar)
{
    int dir = (blockIdx.x >= RB) ? 1 : 0;
    int blk = blockIdx.x - dir * RB;
    const float* pre = dir ? pre_b : pre_f;
    const float* whh = dir ? whh_b : whh_f;
    int* ctr = bar + (size_t)dir * L * STEP_INTS;
    int dir_off = dir * H;
    int mygrp = blk >> 3;

    __shared__ float gates[2][32];

    int tid = threadIdx.x, lane = tid & 31, w = tid >> 5;
    int u0 = blk * 8;
    int lr0 = w * 4;

    // 4 gate rows owned by this warp: lr = lr0+i, row = (lr>>3)*H + u0 + (lr&7)
    const float* rw0; const float* rw1; const float* rw2; const float* rw3;
    int rowidx[4];
#pragma unroll
    for (int i = 0; i < 4; i++) {
        int lr = lr0 + i;
        rowidx[i] = (lr >> 3) * H + u0 + (lr & 7);
    }
    rw0 = whh + (size_t)rowidx[0] * H;
    rw1 = whh + (size_t)rowidx[1] * H;
    rw2 = whh + (size_t)rowidx[2] * H;
    rw3 = whh + (size_t)rowidx[3] * H;

    // pre prefetch: lane i<4 holds pre[t][rowidx[i]] (register double buffer)
    int t0 = dir ? (L - 1) : 0;
    float pf = 0.0f;
    if (lane < 4) pf = __ldcg(&pre[(size_t)t0 * G + rowidx[lane]]);

    float c_state = 0.0f;  // warp 7 lanes 0-7

    for (int s = 0; s < L; s++) {
        int t = dir ? (L - 1 - s) : s;
        int tn = dir ? (t - 1) : (t + 1);
        int tp = dir ? (t + 1) : (t - 1);

        float pcur = pf;  // this step's pre (lanes 0-3)
        if (lane < 4 && s + 1 < L) pf = __ldcg(&pre[(size_t)tn * G + rowidx[lane]]);

        float a0 = 0.f, a1 = 0.f, a2 = 0.f, a3 = 0.f;

        if (s > 0) {
            const float* hvecp = out + (size_t)tp * XW + dir_off;
            const int* cbase = ctr + (size_t)(s - 1) * STEP_INTS;

            // single parallel probe of all 8 group counters
            int v = 0;
            if (lane < 8) {
                asm volatile("ld.acquire.gpu.global.s32 %0, [%1];"
                             : "=r"(v) : "l"(cbase + lane * GSTRIDE) : "memory");
            }
            unsigned rdy = __ballot_sync(0xffffffffu, (lane < 8) && (v >= 8)) & 0xffu;
            unsigned mis = 0xffu & ~rdy;

            // wave 1: fold ready chunks (overlaps laggards' publish latency)
            unsigned m = rdy;
            while (m) {
                int g = __ffs(m) - 1; m &= m - 1;
                float2 hv = __ldcg((const float2*)(hvecp + g * 64) + lane);
                int off = g * 64 + lane * 2;
                float2 wv;
                wv = *(const float2*)(rw0 + off); a0 += wv.x * hv.x + wv.y * hv.y;
                wv = *(const float2*)(rw1 + off); a1 += wv.x * hv.x + wv.y * hv.y;
                wv = *(const float2*)(rw2 + off); a2 += wv.x * hv.x + wv.y * hv.y;
                wv = *(const float2*)(rw3 + off); a3 += wv.x * hv.x + wv.y * hv.y;
            }
            // wave 2: spin on each missing chunk, fold as it lands
            m = mis;
            while (m) {
                int g = __ffs(m) - 1; m &= m - 1;
                if (lane == 0) {
                    int vv;
                    do {
                        asm volatile("ld.acquire.gpu.global.s32 %0, [%1];"
                                     : "=r"(vv) : "l"(cbase + g * GSTRIDE) : "memory");
                    } while (vv < 8);
                }
                __syncwarp();
                float2 hv = __ldcg((const float2*)(hvecp + g * 64) + lane);
                int off = g * 64 + lane * 2;
                float2 wv;
                wv = *(const float2*)(rw0 + off); a0 += wv.x * hv.x + wv.y * hv.y;
                wv = *(const float2*)(rw1 + off); a1 += wv.x * hv.x + wv.y * hv.y;
                wv = *(const float2*)(rw2 + off); a2 += wv.x * hv.x + wv.y * hv.y;
                wv = *(const float2*)(rw3 + off); a3 += wv.x * hv.x + wv.y * hv.y;
            }
        }

        a0 = warp_sum(a0);
        a1 = warp_sum(a1);
        a2 = warp_sum(a2);
        a3 = warp_sum(a3);

        float p0 = __shfl_sync(0xffffffffu, pcur, 0);
        float p1 = __shfl_sync(0xffffffffu, pcur, 1);
        float p2 = __shfl_sync(0xffffffffu, pcur, 2);
        float p3 = __shfl_sync(0xffffffffu, pcur, 3);

        if (lane == 0) {
            gates[s & 1][lr0 + 0] = a0 + p0;
            gates[s & 1][lr0 + 1] = a1 + p1;
            gates[s & 1][lr0 + 2] = a2 + p2;
            gates[s & 1][lr0 + 3] = a3 + p3;
        }
        __syncthreads();   // the ONE block barrier per step

        // warp 7: nonlinearities (32 in parallel), c-update, publish
        if (w == 7) {
            float z = gates[s & 1][lane];
            float nlv = ((lane >> 3) == 2) ? tanh_fast(z) : sigmoid_fast(z);
            int uu = lane & 7;
            float fv = __shfl_sync(0xffffffffu, nlv, 8 + uu);
            float gv = __shfl_sync(0xffffffffu, nlv, 16 + uu);
            float ov = __shfl_sync(0xffffffffu, nlv, 24 + uu);
            if (lane < 8) {
                float iv = nlv;   // lanes 0-7 hold the i-gate
                c_state = fv * c_state + iv * gv;
                float hv = ov * tanh_fast(c_state);
                __stcg(out + (size_t)t * XW + dir_off + u0 + lane, hv);
            }
            __syncwarp();
            if (lane == 0) {
                int old;
                asm volatile("atom.release.gpu.global.add.s32 %0, [%1], %2;"
                             : "=r"(old)
                             : "l"(ctr + (size_t)s * STEP_INTS + mygrp * GSTRIDE), "r"(1)
                             : "memory");
            }
        }
        // other warps roll straight into the next step; their probe/spin is the flow control
    }
}

// ------------------------ emissions: e[L,24] = x2 @ w_out^T + b_out ------------------------
__global__ __launch_bounds__(256) void emis_kernel(
    const float* __restrict__ w_out, const float* __restrict__ b_out)
{
    int tid = threadIdx.x, lane = tid & 31, w = tid >> 5;
    int t = blockIdx.x * 8 + w;
    const float4* xp = (const float4*)(g_x2 + (size_t)t * XW);
    float4 xr[8];
#pragma unroll
    for (int q = 0; q < 8; q++) xr[q] = xp[lane + q * 32];
    for (int j = 0; j < TT; j++) {
        const float4* wp = (const float4*)(w_out + (size_t)j * XW);
        float acc = 0.0f;
#pragma unroll
        for (int q = 0; q < 8; q++) {
            float4 wv = wp[lane + q * 32];
            acc += xr[q].x * wv.x + xr[q].y * wv.y + xr[q].z * wv.z + xr[q].w * wv.w;
        }
        acc = warp_sum(acc);
        if (lane == 0) g_emis[(size_t)t * TT + j] = acc + b_out[j];
    }
}

// ------------------------ CRF NLL ------------------------
__global__ __launch_bounds__(768) void crf_kernel(
    const float* __restrict__ start_trans, const float* __restrict__ end_trans,
    const float* __restrict__ trans, const int* __restrict__ tags,
    float* __restrict__ outp)
{
    __shared__ float trans_sh[TT * 25];
    __shared__ float alpha[2][TT];
    __shared__ float red[24];
    __shared__ float num_sh;

    int tid = threadIdx.x, lane = tid & 31, w = tid >> 5;

    // numerator (parallel part)
    float p = 0.0f;
    for (int t = tid; t < L; t += 768) p += g_emis[(size_t)t * TT + tags[t]];
    for (int t = tid; t < L - 1; t += 768) p += trans[tags[t] * TT + tags[t + 1]];
    p = warp_sum(p);
    if (lane == 0) red[w] = p;

    for (int i = tid; i < TT * TT; i += 768)
        trans_sh[(i / TT) * 25 + (i % TT)] = trans[i];
    if (tid < TT) alpha[0][tid] = start_trans[tid] + g_emis[tid];
    __syncthreads();

    if (w == 0) {
        float q = (lane < 24) ? red[lane] : 0.0f;
        q = warp_sum(q);
        if (lane == 0) num_sh = q + start_trans[tags[0]] + end_trans[tags[L - 1]];
    }
    __syncthreads();

    // forward scan: warp j computes alpha'[j] = logsumexp_i(alpha[i] + trans[i][j]) + e[t][j]
    for (int t = 1; t < L; t++) {
        int cur = t & 1, prv = cur ^ 1;
        if (w < TT) {
            float v = (lane < TT) ? alpha[prv][lane] + trans_sh[lane * 25 + w] : -1e30f;
            float m = warp_max_all(v);
            float e = (lane < TT) ? __expf(v - m) : 0.0f;
            float ssum = warp_sum(e);
            if (lane == 0) alpha[cur][w] = m + logf(ssum) + g_emis[(size_t)t * TT + w];
        }
        __syncthreads();
    }

    if (tid < 32) {
        int tl = (L - 1) & 1;
        float v = (lane < TT) ? alpha[tl][lane] + end_trans[lane] : -1e30f;
        float m = warp_max_all(v);
        float e = (lane < TT) ? __expf(v - m) : 0.0f;
        float ssum = warp_sum(e);
        if (lane == 0) outp[0] = (m + logf(ssum)) - num_sh;
    }
}

// ------------------------ launch ------------------------
extern "C" void kernel_launch(void* const* d_in, const int* in_sizes, int n_in,
                              void* d_out, int out_size)
{
    const float* emb       = (const float*)d_in[0];
    const float* w_ih_l0f  = (const float*)d_in[1];
    const float* w_hh_l0f  = (const float*)d_in[2];
    const float* b_l0f     = (const float*)d_in[3];
    const float* w_ih_l0b  = (const float*)d_in[4];
    const float* w_hh_l0b  = (const float*)d_in[5];
    const float* b_l0b     = (const float*)d_in[6];
    const float* w_ih_l1f  = (const float*)d_in[7];
    const float* w_hh_l1f  = (const float*)d_in[8];
    const float* b_l1f     = (const float*)d_in[9];
    const float* w_ih_l1b  = (const float*)d_in[10];
    const float* w_hh_l1b  = (const float*)d_in[11];
    const float* b_l1b     = (const float*)d_in[12];
    const float* w_out     = (const float*)d_in[13];
    const float* b_out     = (const float*)d_in[14];
    const float* start_tr  = (const float*)d_in[15];
    const float* end_tr    = (const float*)d_in[16];
    const float* trans     = (const float*)d_in[17];
    const int*   sentence  = (const int*)d_in[18];
    const int*   tags      = (const int*)d_in[19];
    float* outp = (float*)d_out;

    float *pre0f, *pre0b, *pre1f, *pre1b, *x1, *x2;
    int* bar;
    cudaGetSymbolAddress((void**)&pre0f, g_pre0f);
    cudaGetSymbolAddress((void**)&pre0b, g_pre0b);
    cudaGetSymbolAddress((void**)&pre1f, g_pre1f);
    cudaGetSymbolAddress((void**)&pre1b, g_pre1b);
    cudaGetSymbolAddress((void**)&x1, g_x1);
    cudaGetSymbolAddress((void**)&x2, g_x2);
    cudaGetSymbolAddress((void**)&bar, g_bar);

    cudaMemsetAsync(bar, 0, (size_t)2 * 2 * L * STEP_INTS * sizeof(int));

    dim3 ggrid(G / 128, L / 128, 2);  // (16, 32, 2)

    // layer 0 input pre-activations (with embedding gather), both directions
    gemm_bias2_kernel<<<ggrid, 256>>>(emb, sentence,
                                      w_ih_l0f, b_l0f, pre0f,
                                      w_ih_l0b, b_l0b, pre0b, L, G, E);

    // layer 0 recurrence -> x1 = concat(hf, hb)
    lstm_kernel<<<2 * RB, RTH>>>(pre0f, pre0b, w_hh_l0f, w_hh_l0b, x1, bar);

    // layer 1 input pre-activations
    gemm_bias2_kernel<<<ggrid, 256>>>(x1, nullptr,
                                      w_ih_l1f, b_l1f, pre1f,
                                      w_ih_l1b, b_l1b, pre1b, L, G, XW);

    // layer 1 recurrence -> x2
    lstm_kernel<<<2 * RB, RTH>>>(pre1f, pre1b, w_hh_l1f, w_hh_l1b, x2,
                                 bar + (size_t)2 * L * STEP_INTS);

    // emissions + CRF
    emis_kernel<<<L / 8, 256>>>(w_out, b_out);
    crf_kernel<<<1, 768>>>(start_tr, end_tr, trans, tags, outp);
}

// round 10
// speedup vs baseline: 1.8558x; 1.8558x over previous
#include <cuda_runtime.h>
#include <cuda_bf16.h>
#include <math.h>

#define L 4096
#define E 300
#define H 512
#define G 2048   // 4*H
#define TT 24
#define XW 1024  // 2*H

#define RB 64      // blocks per LSTM direction
#define RTH 256    // threads per LSTM block
#define NGRP 8     // arrival groups per step (8 blocks per group)
#define GSTRIDE 64 // ints between group counters (256B apart)
#define STEP_INTS (NGRP * GSTRIDE)   // 512 ints per step
#define HXS 2048   // floats per step in the padded h exchange region (64 blocks * 128B)

// ------------------------ scratch (no allocs allowed) ------------------------
__device__ float g_pre0f[(size_t)L * G];
__device__ float g_pre0b[(size_t)L * G];
__device__ float g_pre1f[(size_t)L * G];
__device__ float g_pre1b[(size_t)L * G];
__device__ float g_x1[(size_t)L * XW];
__device__ float g_x2[(size_t)L * XW];
__device__ float g_emis[(size_t)L * TT];
__device__ float g_hx[(size_t)2 * L * HXS];             // padded h exchange (shared by both layers)
__device__ int   g_bar[(size_t)2 * 2 * L * STEP_INTS];  // [layer][dir][step][group]

// ------------------------ helpers ------------------------
__device__ __forceinline__ float warp_sum(float v) {
#pragma unroll
    for (int o = 16; o > 0; o >>= 1) v += __shfl_down_sync(0xffffffffu, v, o);
    return v;
}
__device__ __forceinline__ float warp_max_all(float v) {
#pragma unroll
    for (int o = 16; o > 0; o >>= 1) v = fmaxf(v, __shfl_xor_sync(0xffffffffu, v, o));
    return v;
}
// proven in round 9 (rel_err 0.0)
__device__ __forceinline__ float sigmoid_fast(float x) {
    return __fdividef(1.0f, 1.0f + __expf(-x));
}
__device__ __forceinline__ float tanh_fast(float x) {
    return 1.0f - __fdividef(2.0f, __expf(2.0f * x) + 1.0f);
}

// ------------------------ dual GEMM: C[M,N] = A[M,K] @ B[N,K]^T + bias[N] ------------------------
// Register double-buffered global loads; blockIdx.z selects weight set.
__global__ __launch_bounds__(256) void gemm_bias2_kernel(
    const float* __restrict__ A, const int* __restrict__ rowmap,
    const float* __restrict__ B0, const float* __restrict__ bias0, float* __restrict__ C0,
    const float* __restrict__ B1, const float* __restrict__ bias1, float* __restrict__ C1,
    int M, int N, int K)
{
    const float* B    = blockIdx.z ? B1    : B0;
    const float* bias = blockIdx.z ? bias1 : bias0;
    float*       C    = blockIdx.z ? C1    : C0;

    __shared__ float As[8][128];
    __shared__ float Bs[8][128];

    int tid = threadIdx.x;
    int bm = blockIdx.y, bn = blockIdx.x;
    int tx = tid & 15, ty = tid >> 4;

    int loadRow = tid >> 1;            // 0..127
    int loadCol = (tid & 1) * 4;       // 0 or 4

    int aRowG = bm * 128 + loadRow;
    int aPhys = rowmap ? rowmap[aRowG] : aRowG;
    const float* Aptr = A + (size_t)aPhys * K;
    const float* Bptr = B + (size_t)(bn * 128 + loadRow) * K;

    auto g4 = [K](const float* p, int k) -> float4 {
        if (k + 3 < K) return *(const float4*)(p + k);
        float4 v;
        v.x = (k     < K) ? p[k]     : 0.0f;
        v.y = (k + 1 < K) ? p[k + 1] : 0.0f;
        v.z = (k + 2 < K) ? p[k + 2] : 0.0f;
        v.w = (k + 3 < K) ? p[k + 3] : 0.0f;
        return v;
    };

    float acc[8][8];
#pragma unroll
    for (int i = 0; i < 8; i++)
#pragma unroll
        for (int j = 0; j < 8; j++) acc[i][j] = 0.0f;

    float4 ra = g4(Aptr, loadCol);
    float4 rb = g4(Bptr, loadCol);

    for (int k0 = 0; k0 < K; k0 += 8) {
        As[loadCol + 0][loadRow] = ra.x;
        As[loadCol + 1][loadRow] = ra.y;
        As[loadCol + 2][loadRow] = ra.z;
        As[loadCol + 3][loadRow] = ra.w;
        Bs[loadCol + 0][loadRow] = rb.x;
        Bs[loadCol + 1][loadRow] = rb.y;
        Bs[loadCol + 2][loadRow] = rb.z;
        Bs[loadCol + 3][loadRow] = rb.w;
        __syncthreads();

        if (k0 + 8 < K) {                      // prefetch next tile during compute
            ra = g4(Aptr, k0 + 8 + loadCol);
            rb = g4(Bptr, k0 + 8 + loadCol);
        }

#pragma unroll
        for (int kk = 0; kk < 8; kk++) {
            float a[8], b[8];
#pragma unroll
            for (int i = 0; i < 8; i++) a[i] = As[kk][ty * 8 + i];
#pragma unroll
            for (int j = 0; j < 8; j++) b[j] = Bs[kk][tx * 8 + j];
#pragma unroll
            for (int i = 0; i < 8; i++)
#pragma unroll
                for (int j = 0; j < 8; j++) acc[i][j] += a[i] * b[j];
        }
        __syncthreads();
    }

#pragma unroll
    for (int i = 0; i < 8; i++) {
        int row = bm * 128 + ty * 8 + i;
#pragma unroll
        for (int j = 0; j < 8; j++) {
            int col = bn * 128 + tx * 8 + j;
            C[(size_t)row * N + col] = acc[i][j] + bias[col];
        }
    }
}

// ------------------------ persistent bidirectional LSTM layer ------------------------
// R6 protocol (proven), with: (1) h exchanged via PADDED hx buffer (128B per producer
// block per step -> spreads the broadcast over ~16 L2 slices instead of ~4);
// (2) publish via warp0 __syncwarp + lane0 fence + atom.release (drops one block bar);
// (3) fast nonlinearities (round-9-proven). 3 __syncthreads per step.
__global__ __launch_bounds__(RTH) void lstm_kernel(
    const float* __restrict__ pre_f, const float* __restrict__ pre_b,
    const float* __restrict__ whh_f, const float* __restrict__ whh_b,
    float* __restrict__ out, float* __restrict__ hx, int* __restrict__ bar)
{
    int dir = (blockIdx.x >= RB) ? 1 : 0;
    int blk = blockIdx.x - dir * RB;
    const float* pre = dir ? pre_b : pre_f;
    const float* whh = dir ? whh_b : whh_f;
    int* ctr = bar + (size_t)dir * L * STEP_INTS;
    float* hxd = hx + (size_t)dir * L * HXS;
    int dir_off = dir * H;
    int mygrp = blk >> 3;

    __shared__ float h_sh[H];
    __shared__ float gates[2][32];
    __shared__ float pre_sh[2][32];

    int tid = threadIdx.x, lane = tid & 31, w = tid >> 5;
    int u0 = blk * 8;

    // gate row owned by tid (tid<32 prefetches pre for this row)
    int myrow = (tid >> 3) * H + u0 + (tid & 7);

    int t0 = dir ? (L - 1) : 0;
    if (tid < 32) pre_sh[0][tid] = __ldcg(&pre[(size_t)t0 * G + myrow]);

    float c_state = 0.0f;  // warp 0 lanes 0-7
    __syncthreads();

    for (int s = 0; s < L; s++) {
        int t = dir ? (L - 1 - s) : s;
        int tn = dir ? (t - 1) : (t + 1);
        int tp = dir ? (t + 1) : (t - 1);

        // prefetch pre for step s+1 (hidden behind barrier + matvec)
        float pf = 0.0f;
        if (tid < 32 && s + 1 < L) pf = __ldcg(&pre[(size_t)tn * G + myrow]);

        // wait: all 8 group counters of step s-1 must reach 8 (acquire polls)
        if (s > 0) {
            if (tid < NGRP) {
                const int* addr = ctr + (size_t)(s - 1) * STEP_INTS + tid * GSTRIDE;
                int v;
                do {
                    asm volatile("ld.acquire.gpu.global.s32 %0, [%1];" : "=r"(v) : "l"(addr) : "memory");
                } while (v < 8);
            }
            __syncthreads();   // bar 1: step released
        }

        // load h(prev) from the padded exchange buffer into h_sh
        // thread tt<128: producer block b = tt>>1, 16B at sub-offset (tt&1)*4
        if (tid < 128) {
            float4 hv;
            if (s == 0) {
                hv = make_float4(0.f, 0.f, 0.f, 0.f);
            } else {
                const float* src = hxd + (size_t)tp * HXS + (tid >> 1) * 32 + (tid & 1) * 4;
                hv = __ldcg((const float4*)src);
            }
            ((float4*)h_sh)[tid] = hv;
        }
        __syncthreads();   // bar 2: h_sh ready

        // hoist h into registers (one pass over h_sh per warp)
        float4 hr[4];
#pragma unroll
        for (int q = 0; q < 4; q++) hr[q] = ((const float4*)h_sh)[lane + q * 32];

        // 32 gate rows per block: warp w handles rows lr = w*4 .. w*4+3
#pragma unroll
        for (int i = 0; i < 4; i++) {
            int lr = w * 4 + i;
            int row = (lr >> 3) * H + u0 + (lr & 7);
            const float4* wp = (const float4*)(whh + (size_t)row * H);
            float acc = 0.0f;
#pragma unroll
            for (int q = 0; q < 4; q++) {
                float4 a = wp[lane + q * 32];
                acc += a.x * hr[q].x + a.y * hr[q].y + a.z * hr[q].z + a.w * hr[q].w;
            }
            acc = warp_sum(acc);
            if (lane == 0) gates[s & 1][lr] = acc + pre_sh[s & 1][lr];
        }
        // stage next step's pre (opposite slot; readers ordered by bar 3)
        if (tid < 32 && s + 1 < L) pre_sh[(s + 1) & 1][tid] = pf;
        __syncthreads();   // bar 3: gates ready

        // warp 0: activation + publish (no extra block barrier)
        if (w == 0) {
            if (lane < 8) {
                float iv = sigmoid_fast(gates[s & 1][lane]);
                float fv = sigmoid_fast(gates[s & 1][8 + lane]);
                float gv = tanh_fast(gates[s & 1][16 + lane]);
                float ov = sigmoid_fast(gates[s & 1][24 + lane]);
                c_state = fv * c_state + iv * gv;
                float hv = ov * tanh_fast(c_state);
                __stcg(hxd + (size_t)t * HXS + blk * 32 + lane, hv);       // exchange copy
                __stcg(out + (size_t)t * XW + dir_off + u0 + lane, hv);    // GEMM copy
            }
            __syncwarp();
            if (lane == 0) {
                __threadfence();
                int old;
                asm volatile("atom.release.gpu.global.add.s32 %0, [%1], %2;"
                             : "=r"(old)
                             : "l"(ctr + (size_t)s * STEP_INTS + mygrp * GSTRIDE), "r"(1)
                             : "memory");
            }
        }
        // warps 1-7 roll into the next step immediately; bar 1 gates them
    }
}

// ------------------------ emissions: e[L,24] = x2 @ w_out^T + b_out ------------------------
__global__ __launch_bounds__(256) void emis_kernel(
    const float* __restrict__ w_out, const float* __restrict__ b_out)
{
    int tid = threadIdx.x, lane = tid & 31, w = tid >> 5;
    int t = blockIdx.x * 8 + w;
    const float4* xp = (const float4*)(g_x2 + (size_t)t * XW);
    float4 xr[8];
#pragma unroll
    for (int q = 0; q < 8; q++) xr[q] = xp[lane + q * 32];
    for (int j = 0; j < TT; j++) {
        const float4* wp = (const float4*)(w_out + (size_t)j * XW);
        float acc = 0.0f;
#pragma unroll
        for (int q = 0; q < 8; q++) {
            float4 wv = wp[lane + q * 32];
            acc += xr[q].x * wv.x + xr[q].y * wv.y + xr[q].z * wv.z + xr[q].w * wv.w;
        }
        acc = warp_sum(acc);
        if (lane == 0) g_emis[(size_t)t * TT + j] = acc + b_out[j];
    }
}

// ------------------------ CRF NLL ------------------------
__global__ __launch_bounds__(768) void crf_kernel(
    const float* __restrict__ start_trans, const float* __restrict__ end_trans,
    const float* __restrict__ trans, const int* __restrict__ tags,
    float* __restrict__ outp)
{
    __shared__ float trans_sh[TT * 25];
    __shared__ float alpha[2][TT];
    __shared__ float red[24];
    __shared__ float num_sh;

    int tid = threadIdx.x, lane = tid & 31, w = tid >> 5;

    // numerator (parallel part)
    float p = 0.0f;
    for (int t = tid; t < L; t += 768) p += g_emis[(size_t)t * TT + tags[t]];
    for (int t = tid; t < L - 1; t += 768) p += trans[tags[t] * TT + tags[t + 1]];
    p = warp_sum(p);
    if (lane == 0) red[w] = p;

    for (int i = tid; i < TT * TT; i += 768)
        trans_sh[(i / TT) * 25 + (i % TT)] = trans[i];
    if (tid < TT) alpha[0][tid] = start_trans[tid] + g_emis[tid];
    __syncthreads();

    if (w == 0) {
        float q = (lane < 24) ? red[lane] : 0.0f;
        q = warp_sum(q);
        if (lane == 0) num_sh = q + start_trans[tags[0]] + end_trans[tags[L - 1]];
    }
    __syncthreads();

    // forward scan: warp j computes alpha'[j] = logsumexp_i(alpha[i] + trans[i][j]) + e[t][j]
    for (int t = 1; t < L; t++) {
        int cur = t & 1, prv = cur ^ 1;
        if (w < TT) {
            float v = (lane < TT) ? alpha[prv][lane] + trans_sh[lane * 25 + w] : -1e30f;
            float m = warp_max_all(v);
            float e = (lane < TT) ? __expf(v - m) : 0.0f;
            float ssum = warp_sum(e);
            if (lane == 0) alpha[cur][w] = m + logf(ssum) + g_emis[(size_t)t * TT + w];
        }
        __syncthreads();
    }

    if (tid < 32) {
        int tl = (L - 1) & 1;
        float v = (lane < TT) ? alpha[tl][lane] + end_trans[lane] : -1e30f;
        float m = warp_max_all(v);
        float e = (lane < TT) ? __expf(v - m) : 0.0f;
        float ssum = warp_sum(e);
        if (lane == 0) outp[0] = (m + logf(ssum)) - num_sh;
    }
}

// ------------------------ launch ------------------------
extern "C" void kernel_launch(void* const* d_in, const int* in_sizes, int n_in,
                              void* d_out, int out_size)
{
    const float* emb       = (const float*)d_in[0];
    const float* w_ih_l0f  = (const float*)d_in[1];
    const float* w_hh_l0f  = (const float*)d_in[2];
    const float* b_l0f     = (const float*)d_in[3];
    const float* w_ih_l0b  = (const float*)d_in[4];
    const float* w_hh_l0b  = (const float*)d_in[5];
    const float* b_l0b     = (const float*)d_in[6];
    const float* w_ih_l1f  = (const float*)d_in[7];
    const float* w_hh_l1f  = (const float*)d_in[8];
    const float* b_l1f     = (const float*)d_in[9];
    const float* w_ih_l1b  = (const float*)d_in[10];
    const float* w_hh_l1b  = (const float*)d_in[11];
    const float* b_l1b     = (const float*)d_in[12];
    const float* w_out     = (const float*)d_in[13];
    const float* b_out     = (const float*)d_in[14];
    const float* start_tr  = (const float*)d_in[15];
    const float* end_tr    = (const float*)d_in[16];
    const float* trans     = (const float*)d_in[17];
    const int*   sentence  = (const int*)d_in[18];
    const int*   tags      = (const int*)d_in[19];
    float* outp = (float*)d_out;

    float *pre0f, *pre0b, *pre1f, *pre1b, *x1, *x2, *hx;
    int* bar;
    cudaGetSymbolAddress((void**)&pre0f, g_pre0f);
    cudaGetSymbolAddress((void**)&pre0b, g_pre0b);
    cudaGetSymbolAddress((void**)&pre1f, g_pre1f);
    cudaGetSymbolAddress((void**)&pre1b, g_pre1b);
    cudaGetSymbolAddress((void**)&x1, g_x1);
    cudaGetSymbolAddress((void**)&x2, g_x2);
    cudaGetSymbolAddress((void**)&hx, g_hx);
    cudaGetSymbolAddress((void**)&bar, g_bar);

    cudaMemsetAsync(bar, 0, (size_t)2 * 2 * L * STEP_INTS * sizeof(int));

    dim3 ggrid(G / 128, L / 128, 2);  // (16, 32, 2)

    // layer 0 input pre-activations (with embedding gather), both directions
    gemm_bias2_kernel<<<ggrid, 256>>>(emb, sentence,
                                      w_ih_l0f, b_l0f, pre0f,
                                      w_ih_l0b, b_l0b, pre0b, L, G, E);

    // layer 0 recurrence -> x1 = concat(hf, hb)
    lstm_kernel<<<2 * RB, RTH>>>(pre0f, pre0b, w_hh_l0f, w_hh_l0b, x1, hx, bar);

    // layer 1 input pre-activations
    gemm_bias2_kernel<<<ggrid, 256>>>(x1, nullptr,
                                      w_ih_l1f, b_l1f, pre1f,
                                      w_ih_l1b, b_l1b, pre1b, L, G, XW);

    // layer 1 recurrence -> x2 (reuses hx; gated by its own counters)
    lstm_kernel<<<2 * RB, RTH>>>(pre1f, pre1b, w_hh_l1f, w_hh_l1b, x2, hx,
                                 bar + (size_t)2 * L * STEP_INTS);

    // emissions + CRF
    emis_kernel<<<L / 8, 256>>>(w_out, b_out);
    crf_kernel<<<1, 768>>>(start_tr, end_tr, trans, tags, outp);
}

// round 11
// speedup vs baseline: 3.1454x; 1.6949x over previous
#include <cuda_runtime.h>
#include <cuda_bf16.h>
#include <math.h>

#define L 4096
#define E 300
#define H 512
#define G 2048   // 4*H
#define TT 24
#define XW 1024  // 2*H

#define RB 64      // blocks per LSTM direction
#define RTH 256    // threads per LSTM block
#define NGRP 8     // arrival groups per step (8 blocks per group)
#define GSTRIDE 64 // ints between group counters (256B apart)
#define STEP_INTS (NGRP * GSTRIDE)   // 512 ints per step

// ------------------------ scratch (no allocs allowed) ------------------------
__device__ float g_pre0f[(size_t)L * G];
__device__ float g_pre0b[(size_t)L * G];
__device__ float g_pre1f[(size_t)L * G];
__device__ float g_pre1b[(size_t)L * G];
__device__ float g_x1[(size_t)L * XW];
__device__ float g_x2[(size_t)L * XW];
__device__ float g_emis[(size_t)L * TT];
__device__ int   g_bar[(size_t)2 * 2 * L * STEP_INTS];  // [layer][dir][step][group]

// ------------------------ helpers ------------------------
__device__ __forceinline__ float warp_sum(float v) {
#pragma unroll
    for (int o = 16; o > 0; o >>= 1) v += __shfl_down_sync(0xffffffffu, v, o);
    return v;
}
__device__ __forceinline__ float warp_max_all(float v) {
#pragma unroll
    for (int o = 16; o > 0; o >>= 1) v = fmaxf(v, __shfl_xor_sync(0xffffffffu, v, o));
    return v;
}
// proven rounds 9/10 (rel_err 0.0)
__device__ __forceinline__ float sigmoid_fast(float x) {
    return __fdividef(1.0f, 1.0f + __expf(-x));
}
__device__ __forceinline__ float tanh_fast(float x) {
    return 1.0f - __fdividef(2.0f, __expf(2.0f * x) + 1.0f);
}

// ------------------------ dual GEMM: C[M,N] = A[M,K] @ B[N,K]^T + bias[N] ------------------------
// (round-6 proven form) blockIdx.z selects weight set. BM=BN=128, BK=8, 8x8 microtile.
__global__ __launch_bounds__(256) void gemm_bias2_kernel(
    const float* __restrict__ A, const int* __restrict__ rowmap,
    const float* __restrict__ B0, const float* __restrict__ bias0, float* __restrict__ C0,
    const float* __restrict__ B1, const float* __restrict__ bias1, float* __restrict__ C1,
    int M, int N, int K)
{
    const float* B    = blockIdx.z ? B1    : B0;
    const float* bias = blockIdx.z ? bias1 : bias0;
    float*       C    = blockIdx.z ? C1    : C0;

    __shared__ float As[8][128];
    __shared__ float Bs[8][128];

    int tid = threadIdx.x;
    int bm = blockIdx.y, bn = blockIdx.x;
    int tx = tid & 15, ty = tid >> 4;

    int loadRow = tid >> 1;            // 0..127
    int loadCol = (tid & 1) * 4;       // 0 or 4

    int aRowG = bm * 128 + loadRow;
    int aPhys = rowmap ? rowmap[aRowG] : aRowG;
    const float* Aptr = A + (size_t)aPhys * K;
    const float* Bptr = B + (size_t)(bn * 128 + loadRow) * K;

    float acc[8][8];
#pragma unroll
    for (int i = 0; i < 8; i++)
#pragma unroll
        for (int j = 0; j < 8; j++) acc[i][j] = 0.0f;

    for (int k0 = 0; k0 < K; k0 += 8) {
        int k = k0 + loadCol;
        if (k + 3 < K) {
            float4 va = *(const float4*)(Aptr + k);
            As[loadCol + 0][loadRow] = va.x;
            As[loadCol + 1][loadRow] = va.y;
            As[loadCol + 2][loadRow] = va.z;
            As[loadCol + 3][loadRow] = va.w;
            float4 vb = *(const float4*)(Bptr + k);
            Bs[loadCol + 0][loadRow] = vb.x;
            Bs[loadCol + 1][loadRow] = vb.y;
            Bs[loadCol + 2][loadRow] = vb.z;
            Bs[loadCol + 3][loadRow] = vb.w;
        } else {
#pragma unroll
            for (int i = 0; i < 4; i++) {
                int kk = k + i;
                As[loadCol + i][loadRow] = (kk < K) ? Aptr[kk] : 0.0f;
                Bs[loadCol + i][loadRow] = (kk < K) ? Bptr[kk] : 0.0f;
            }
        }
        __syncthreads();
#pragma unroll
        for (int kk = 0; kk < 8; kk++) {
            float a[8], b[8];
#pragma unroll
            for (int i = 0; i < 8; i++) a[i] = As[kk][ty * 8 + i];
#pragma unroll
            for (int j = 0; j < 8; j++) b[j] = Bs[kk][tx * 8 + j];
#pragma unroll
            for (int i = 0; i < 8; i++)
#pragma unroll
                for (int j = 0; j < 8; j++) acc[i][j] += a[i] * b[j];
        }
        __syncthreads();
    }

#pragma unroll
    for (int i = 0; i < 8; i++) {
        int row = bm * 128 + ty * 8 + i;
#pragma unroll
        for (int j = 0; j < 8; j++) {
            int col = bn * 128 + tx * 8 + j;
            C[(size_t)row * N + col] = acc[i][j] + bias[col];
        }
    }
}

// ------------------------ persistent bidirectional LSTM layer ------------------------
// FENCE-FREE steady state. All cross-block traffic (h, pre, counters) uses .cg =
// L2-coherent, L1-bypassing; therefore NO gpu-scope fence or acquire is needed on
// the consumer side, and W_hh (default cached loads) stays L1-resident — this is
// the fix for the CCTL.IVALL-per-step L1 flush that dominated rounds 3-10.
// Producer ordering: .cg h stores -> __syncwarp -> atom.release.gpu counter add
// (release orders the prior stores at L2; proven round 7).
// 2 __syncthreads per step. Activation on warp 7 so warp 0 rolls into the next poll.
__global__ __launch_bounds__(RTH) void lstm_kernel(
    const float* __restrict__ pre_f, const float* __restrict__ pre_b,
    const float* __restrict__ whh_f, const float* __restrict__ whh_b,
    float* __restrict__ out, int* __restrict__ bar)
{
    int dir = (blockIdx.x >= RB) ? 1 : 0;
    int blk = blockIdx.x - dir * RB;
    const float* pre = dir ? pre_b : pre_f;
    const float* whh = dir ? whh_b : whh_f;
    int* ctr = bar + (size_t)dir * L * STEP_INTS;
    int dir_off = dir * H;
    int mygrp = blk >> 3;

    __shared__ float gates[2][32];
    __shared__ float pre_sh[2][32];

    int tid = threadIdx.x, lane = tid & 31, w = tid >> 5;
    int u0 = blk * 8;

    // gate row owned by tid (tid<32 prefetches pre for this row)
    int myrow = (tid >> 3) * H + u0 + (tid & 7);

    int t0 = dir ? (L - 1) : 0;
    if (tid < 32) pre_sh[0][tid] = __ldcg(&pre[(size_t)t0 * G + myrow]);

    float c_state = 0.0f;  // warp 7 lanes 0-7
    __syncthreads();

    for (int s = 0; s < L; s++) {
        int t = dir ? (L - 1 - s) : s;
        int tn = dir ? (t - 1) : (t + 1);
        int tp = dir ? (t + 1) : (t - 1);

        // prefetch pre for step s+1 (hidden behind poll + matvec)
        float pf = 0.0f;
        if (tid < 32 && s + 1 < L) pf = __ldcg(&pre[(size_t)tn * G + myrow]);

        // wait: all 8 group counters of step s-1 must reach 8.
        // PLAIN .cg polls — no acquire, no fence (L2 is the coherence point for
        // all .cg traffic; ordering vs h reads is by dependency + bar).
        if (s > 0) {
            if (tid < NGRP) {
                const int* addr = ctr + (size_t)(s - 1) * STEP_INTS + tid * GSTRIDE;
                int v;
                do {
                    asm volatile("ld.global.cg.s32 %0, [%1];" : "=r"(v) : "l"(addr) : "memory");
                } while (v < 8);
            }
            __syncthreads();   // bar 1: step released for all warps
        }

        // each warp loads the full h(prev) directly into registers (.cg, write-once buffer)
        float4 hr[4];
        if (s == 0) {
#pragma unroll
            for (int q = 0; q < 4; q++) hr[q] = make_float4(0.f, 0.f, 0.f, 0.f);
        } else {
            const float4* hp = (const float4*)(out + (size_t)tp * XW + dir_off) + lane;
            hr[0] = __ldcg(hp);
            hr[1] = __ldcg(hp + 32);
            hr[2] = __ldcg(hp + 64);
            hr[3] = __ldcg(hp + 96);
        }

        // 32 gate rows per block: warp w handles rows lr = w*4 .. w*4+3
        // W_hh via DEFAULT loads -> L1-resident across steps (no flushes anymore)
#pragma unroll
        for (int i = 0; i < 4; i++) {
            int lr = w * 4 + i;
            int row = (lr >> 3) * H + u0 + (lr & 7);
            const float4* wp = (const float4*)(whh + (size_t)row * H);
            float acc = 0.0f;
#pragma unroll
            for (int q = 0; q < 4; q++) {
                float4 a = wp[lane + q * 32];
                acc += a.x * hr[q].x + a.y * hr[q].y + a.z * hr[q].z + a.w * hr[q].w;
            }
            acc = warp_sum(acc);
            if (lane == 0) gates[s & 1][lr] = acc + pre_sh[s & 1][lr];
        }
        // stage next step's pre (opposite parity slot; readers ordered by bar 2)
        if (tid < 32 && s + 1 < L) pre_sh[(s + 1) & 1][tid] = pf;
        __syncthreads();   // bar 2: gates ready

        // warp 7: activation + publish; other warps roll straight into next step
        if (w == 7) {
            if (lane < 8) {
                float iv = sigmoid_fast(gates[s & 1][lane]);
                float fv = sigmoid_fast(gates[s & 1][8 + lane]);
                float gv = tanh_fast(gates[s & 1][16 + lane]);
                float ov = sigmoid_fast(gates[s & 1][24 + lane]);
                c_state = fv * c_state + iv * gv;
                float hv = ov * tanh_fast(c_state);
                __stcg(out + (size_t)t * XW + dir_off + u0 + lane, hv);
            }
            __syncwarp();
            if (lane == 0) {
                int old;
                asm volatile("atom.release.gpu.global.add.s32 %0, [%1], %2;"
                             : "=r"(old)
                             : "l"(ctr + (size_t)s * STEP_INTS + mygrp * GSTRIDE), "r"(1)
                             : "memory");
            }
        }
    }
}

// ------------------------ emissions: e[L,24] = x2 @ w_out^T + b_out ------------------------
__global__ __launch_bounds__(256) void emis_kernel(
    const float* __restrict__ w_out, const float* __restrict__ b_out)
{
    int tid = threadIdx.x, lane = tid & 31, w = tid >> 5;
    int t = blockIdx.x * 8 + w;
    const float4* xp = (const float4*)(g_x2 + (size_t)t * XW);
    float4 xr[8];
#pragma unroll
    for (int q = 0; q < 8; q++) xr[q] = xp[lane + q * 32];
    for (int j = 0; j < TT; j++) {
        const float4* wp = (const float4*)(w_out + (size_t)j * XW);
        float acc = 0.0f;
#pragma unroll
        for (int q = 0; q < 8; q++) {
            float4 wv = wp[lane + q * 32];
            acc += xr[q].x * wv.x + xr[q].y * wv.y + xr[q].z * wv.z + xr[q].w * wv.w;
        }
        acc = warp_sum(acc);
        if (lane == 0) g_emis[(size_t)t * TT + j] = acc + b_out[j];
    }
}

// ------------------------ CRF NLL ------------------------
__global__ __launch_bounds__(768) void crf_kernel(
    const float* __restrict__ start_trans, const float* __restrict__ end_trans,
    const float* __restrict__ trans, const int* __restrict__ tags,
    float* __restrict__ outp)
{
    __shared__ float trans_sh[TT * 25];
    __shared__ float alpha[2][TT];
    __shared__ float red[24];
    __shared__ float num_sh;

    int tid = threadIdx.x, lane = tid & 31, w = tid >> 5;

    // numerator (parallel part)
    float p = 0.0f;
    for (int t = tid; t < L; t += 768) p += g_emis[(size_t)t * TT + tags[t]];
    for (int t = tid; t < L - 1; t += 768) p += trans[tags[t] * TT + tags[t + 1]];
    p = warp_sum(p);
    if (lane == 0) red[w] = p;

    for (int i = tid; i < TT * TT; i += 768)
        trans_sh[(i / TT) * 25 + (i % TT)] = trans[i];
    if (tid < TT) alpha[0][tid] = start_trans[tid] + g_emis[tid];
    __syncthreads();

    if (w == 0) {
        float q = (lane < 24) ? red[lane] : 0.0f;
        q = warp_sum(q);
        if (lane == 0) num_sh = q + start_trans[tags[0]] + end_trans[tags[L - 1]];
    }
    __syncthreads();

    // forward scan: warp j computes alpha'[j] = logsumexp_i(alpha[i] + trans[i][j]) + e[t][j]
    for (int t = 1; t < L; t++) {
        int cur = t & 1, prv = cur ^ 1;
        if (w < TT) {
            float v = (lane < TT) ? alpha[prv][lane] + trans_sh[lane * 25 + w] : -1e30f;
            float m = warp_max_all(v);
            float e = (lane < TT) ? __expf(v - m) : 0.0f;
            float ssum = warp_sum(e);
            if (lane == 0) alpha[cur][w] = m + logf(ssum) + g_emis[(size_t)t * TT + w];
        }
        __syncthreads();
    }

    if (tid < 32) {
        int tl = (L - 1) & 1;
        float v = (lane < TT) ? alpha[tl][lane] + end_trans[lane] : -1e30f;
        float m = warp_max_all(v);
        float e = (lane < TT) ? __expf(v - m) : 0.0f;
        float ssum = warp_sum(e);
        if (lane == 0) outp[0] = (m + logf(ssum)) - num_sh;
    }
}

// ------------------------ launch ------------------------
extern "C" void kernel_launch(void* const* d_in, const int* in_sizes, int n_in,
                              void* d_out, int out_size)
{
    const float* emb       = (const float*)d_in[0];
    const float* w_ih_l0f  = (const float*)d_in[1];
    const float* w_hh_l0f  = (const float*)d_in[2];
    const float* b_l0f     = (const float*)d_in[3];
    const float* w_ih_l0b  = (const float*)d_in[4];
    const float* w_hh_l0b  = (const float*)d_in[5];
    const float* b_l0b     = (const float*)d_in[6];
    const float* w_ih_l1f  = (const float*)d_in[7];
    const float* w_hh_l1f  = (const float*)d_in[8];
    const float* b_l1f     = (const float*)d_in[9];
    const float* w_ih_l1b  = (const float*)d_in[10];
    const float* w_hh_l1b  = (const float*)d_in[11];
    const float* b_l1b     = (const float*)d_in[12];
    const float* w_out     = (const float*)d_in[13];
    const float* b_out     = (const float*)d_in[14];
    const float* start_tr  = (const float*)d_in[15];
    const float* end_tr    = (const float*)d_in[16];
    const float* trans     = (const float*)d_in[17];
    const int*   sentence  = (const int*)d_in[18];
    const int*   tags      = (const int*)d_in[19];
    float* outp = (float*)d_out;

    float *pre0f, *pre0b, *pre1f, *pre1b, *x1, *x2;
    int* bar;
    cudaGetSymbolAddress((void**)&pre0f, g_pre0f);
    cudaGetSymbolAddress((void**)&pre0b, g_pre0b);
    cudaGetSymbolAddress((void**)&pre1f, g_pre1f);
    cudaGetSymbolAddress((void**)&pre1b, g_pre1b);
    cudaGetSymbolAddress((void**)&x1, g_x1);
    cudaGetSymbolAddress((void**)&x2, g_x2);
    cudaGetSymbolAddress((void**)&bar, g_bar);

    cudaMemsetAsync(bar, 0, (size_t)2 * 2 * L * STEP_INTS * sizeof(int));

    dim3 ggrid(G / 128, L / 128, 2);  // (16, 32, 2)

    // layer 0 input pre-activations (with embedding gather), both directions
    gemm_bias2_kernel<<<ggrid, 256>>>(emb, sentence,
                                      w_ih_l0f, b_l0f, pre0f,
                                      w_ih_l0b, b_l0b, pre0b, L, G, E);

    // layer 0 recurrence -> x1 = concat(hf, hb)
    lstm_kernel<<<2 * RB, RTH>>>(pre0f, pre0b, w_hh_l0f, w_hh_l0b, x1, bar);

    // layer 1 input pre-activations
    gemm_bias2_kernel<<<ggrid, 256>>>(x1, nullptr,
                                      w_ih_l1f, b_l1f, pre1f,
                                      w_ih_l1b, b_l1b, pre1b, L, G, XW);

    // layer 1 recurrence -> x2
    lstm_kernel<<<2 * RB, RTH>>>(pre1f, pre1b, w_hh_l1f, w_hh_l1b, x2,
                                 bar + (size_t)2 * L * STEP_INTS);

    // emissions + CRF
    emis_kernel<<<L / 8, 256>>>(w_out, b_out);
    crf_kernel<<<1, 768>>>(start_tr, end_tr, trans, tags, outp);
}

// round 12
// speedup vs baseline: 4.1997x; 1.3352x over previous
#include <cuda_runtime.h>
#include <cuda_bf16.h>
#include <math.h>

#define L 4096
#define E 300
#define H 512
#define G 2048   // 4*H
#define TT 24
#define XW 1024  // 2*H

#define RB 64      // blocks per LSTM direction
#define RTH 256    // threads per LSTM block
#define NGRP 8     // arrival groups per step (8 blocks per group)
#define GSTRIDE 64 // ints between group counters (256B apart)
#define STEP_INTS (NGRP * GSTRIDE)   // 512 ints per step

// ------------------------ scratch (no allocs allowed) ------------------------
__device__ float g_pre0f[(size_t)L * G];
__device__ float g_pre0b[(size_t)L * G];
__device__ float g_pre1f[(size_t)L * G];
__device__ float g_pre1b[(size_t)L * G];
__device__ float g_x1[(size_t)L * XW];
__device__ float g_x2[(size_t)L * XW];
__device__ float g_emis[(size_t)L * TT];
__device__ int   g_bar[(size_t)2 * 2 * L * STEP_INTS];  // [layer][dir][step][group]

// ------------------------ helpers ------------------------
__device__ __forceinline__ float warp_sum(float v) {
#pragma unroll
    for (int o = 16; o > 0; o >>= 1) v += __shfl_down_sync(0xffffffffu, v, o);
    return v;
}
__device__ __forceinline__ float warp_max_all(float v) {
#pragma unroll
    for (int o = 16; o > 0; o >>= 1) v = fmaxf(v, __shfl_xor_sync(0xffffffffu, v, o));
    return v;
}
// proven rounds 9/11 (rel_err 0.0 / 1.4e-4)
__device__ __forceinline__ float sigmoid_fast(float x) {
    return __fdividef(1.0f, 1.0f + __expf(-x));
}
__device__ __forceinline__ float tanh_fast(float x) {
    return 1.0f - __fdividef(2.0f, __expf(2.0f * x) + 1.0f);
}

// ------------------------ dual GEMM: C[M,N] = A[M,K] @ B[N,K]^T + bias[N] ------------------------
// (round-6/11 proven form) blockIdx.z selects weight set. BM=BN=128, BK=8, 8x8 microtile.
__global__ __launch_bounds__(256) void gemm_bias2_kernel(
    const float* __restrict__ A, const int* __restrict__ rowmap,
    const float* __restrict__ B0, const float* __restrict__ bias0, float* __restrict__ C0,
    const float* __restrict__ B1, const float* __restrict__ bias1, float* __restrict__ C1,
    int M, int N, int K)
{
    const float* B    = blockIdx.z ? B1    : B0;
    const float* bias = blockIdx.z ? bias1 : bias0;
    float*       C    = blockIdx.z ? C1    : C0;

    __shared__ float As[8][128];
    __shared__ float Bs[8][128];

    int tid = threadIdx.x;
    int bm = blockIdx.y, bn = blockIdx.x;
    int tx = tid & 15, ty = tid >> 4;

    int loadRow = tid >> 1;            // 0..127
    int loadCol = (tid & 1) * 4;       // 0 or 4

    int aRowG = bm * 128 + loadRow;
    int aPhys = rowmap ? rowmap[aRowG] : aRowG;
    const float* Aptr = A + (size_t)aPhys * K;
    const float* Bptr = B + (size_t)(bn * 128 + loadRow) * K;

    float acc[8][8];
#pragma unroll
    for (int i = 0; i < 8; i++)
#pragma unroll
        for (int j = 0; j < 8; j++) acc[i][j] = 0.0f;

    for (int k0 = 0; k0 < K; k0 += 8) {
        int k = k0 + loadCol;
        if (k + 3 < K) {
            float4 va = *(const float4*)(Aptr + k);
            As[loadCol + 0][loadRow] = va.x;
            As[loadCol + 1][loadRow] = va.y;
            As[loadCol + 2][loadRow] = va.z;
            As[loadCol + 3][loadRow] = va.w;
            float4 vb = *(const float4*)(Bptr + k);
            Bs[loadCol + 0][loadRow] = vb.x;
            Bs[loadCol + 1][loadRow] = vb.y;
            Bs[loadCol + 2][loadRow] = vb.z;
            Bs[loadCol + 3][loadRow] = vb.w;
        } else {
#pragma unroll
            for (int i = 0; i < 4; i++) {
                int kk = k + i;
                As[loadCol + i][loadRow] = (kk < K) ? Aptr[kk] : 0.0f;
                Bs[loadCol + i][loadRow] = (kk < K) ? Bptr[kk] : 0.0f;
            }
        }
        __syncthreads();
#pragma unroll
        for (int kk = 0; kk < 8; kk++) {
            float a[8], b[8];
#pragma unroll
            for (int i = 0; i < 8; i++) a[i] = As[kk][ty * 8 + i];
#pragma unroll
            for (int j = 0; j < 8; j++) b[j] = Bs[kk][tx * 8 + j];
#pragma unroll
            for (int i = 0; i < 8; i++)
#pragma unroll
                for (int j = 0; j < 8; j++) acc[i][j] += a[i] * b[j];
        }
        __syncthreads();
    }

#pragma unroll
    for (int i = 0; i < 8; i++) {
        int row = bm * 128 + ty * 8 + i;
#pragma unroll
        for (int j = 0; j < 8; j++) {
            int col = bn * 128 + tx * 8 + j;
            C[(size_t)row * N + col] = acc[i][j] + bias[col];
        }
    }
}

// ------------------------ persistent bidirectional LSTM layer ------------------------
// FENCE-FREE steady state (round-11 proven; NO gpu-scope fence/acquire anywhere).
// New this round:
//  - FUSED poll+load: tid<128 each polls its OWN group counter (group = tid>>4) with a
//    plain .cg spin, then immediately .cg-loads its float4 of h(prev) into h_sh.
//    Removes the separate poll phase (2 bars/step) and cuts h L2 traffic 8x vs
//    per-warp register loads (256KB/step instead of 2MB -> no LTS queueing spike).
//  - Parallel activation on warp 7: 32 nonlinearities across lanes + 3 shfls
//    (round-9-proven arithmetic), then lanes 0-7 store h, __syncwarp, lane0
//    atom.release.gpu publish (same-warp store->release ordering, round-11 proven).
__global__ __launch_bounds__(RTH) void lstm_kernel(
    const float* __restrict__ pre_f, const float* __restrict__ pre_b,
    const float* __restrict__ whh_f, const float* __restrict__ whh_b,
    float* __restrict__ out, int* __restrict__ bar)
{
    int dir = (blockIdx.x >= RB) ? 1 : 0;
    int blk = blockIdx.x - dir * RB;
    const float* pre = dir ? pre_b : pre_f;
    const float* whh = dir ? whh_b : whh_f;
    int* ctr = bar + (size_t)dir * L * STEP_INTS;
    int dir_off = dir * H;
    int mygrp = blk >> 3;

    __shared__ float h_sh[H];
    __shared__ float gates[2][32];
    __shared__ float pre_sh[2][32];

    int tid = threadIdx.x, lane = tid & 31, w = tid >> 5;
    int u0 = blk * 8;

    // gate row owned by tid (tid<32 prefetches pre for this row)
    int myrow = (tid >> 3) * H + u0 + (tid & 7);

    int t0 = dir ? (L - 1) : 0;
    if (tid < 32) pre_sh[0][tid] = __ldcg(&pre[(size_t)t0 * G + myrow]);

    float c_state = 0.0f;  // warp 7 lanes 0-7
    __syncthreads();

    for (int s = 0; s < L; s++) {
        int t = dir ? (L - 1 - s) : s;
        int tn = dir ? (t - 1) : (t + 1);
        int tp = dir ? (t + 1) : (t - 1);

        // prefetch pre for step s+1 (hidden behind poll + matvec)
        float pf = 0.0f;
        if (tid < 32 && s + 1 < L) pf = __ldcg(&pre[(size_t)tn * G + myrow]);

        // fused poll + h load into smem: thread tid (<128) owns h float4 #tid,
        // whose producer block is tid>>1, group (tid>>1)>>3 = tid>>4.
        if (tid < 128) {
            if (s == 0) {
                ((float4*)h_sh)[tid] = make_float4(0.f, 0.f, 0.f, 0.f);
            } else {
                const int* addr = ctr + (size_t)(s - 1) * STEP_INTS + (tid >> 4) * GSTRIDE;
                int v;
                do {
                    asm volatile("ld.global.cg.s32 %0, [%1];" : "=r"(v) : "l"(addr) : "memory");
                } while (v < 8);
                float4 hv = __ldcg((const float4*)(out + (size_t)tp * XW + dir_off) + tid);
                ((float4*)h_sh)[tid] = hv;
            }
        }
        __syncthreads();   // bar 1: h_sh ready

        // hoist h into registers (one conflict-free LDS pass per warp)
        float4 hr[4];
#pragma unroll
        for (int q = 0; q < 4; q++) hr[q] = ((const float4*)h_sh)[lane + q * 32];

        // 32 gate rows per block: warp w handles rows lr = w*4 .. w*4+3
        // W_hh via DEFAULT loads -> L1-resident across steps (fence-free!)
#pragma unroll
        for (int i = 0; i < 4; i++) {
            int lr = w * 4 + i;
            int row = (lr >> 3) * H + u0 + (lr & 7);
            const float4* wp = (const float4*)(whh + (size_t)row * H);
            float acc = 0.0f;
#pragma unroll
            for (int q = 0; q < 4; q++) {
                float4 a = wp[lane + q * 32];
                acc += a.x * hr[q].x + a.y * hr[q].y + a.z * hr[q].z + a.w * hr[q].w;
            }
            acc = warp_sum(acc);
            if (lane == 0) gates[s & 1][lr] = acc + pre_sh[s & 1][lr];
        }
        // stage next step's pre (opposite parity slot; readers ordered by bar 2)
        if (tid < 32 && s + 1 < L) pre_sh[(s + 1) & 1][tid] = pf;
        __syncthreads();   // bar 2: gates ready

        // warp 7: parallel activation + publish; other warps roll into next poll
        if (w == 7) {
            float z = gates[s & 1][lane];
            float nlv = ((lane >> 3) == 2) ? tanh_fast(z) : sigmoid_fast(z);
            int uu = lane & 7;
            float fv = __shfl_sync(0xffffffffu, nlv, 8 + uu);
            float gv = __shfl_sync(0xffffffffu, nlv, 16 + uu);
            float ov = __shfl_sync(0xffffffffu, nlv, 24 + uu);
            if (lane < 8) {
                c_state = fv * c_state + nlv * gv;   // lanes 0-7 hold the i-gate
                float hv = ov * tanh_fast(c_state);
                __stcg(out + (size_t)t * XW + dir_off + u0 + lane, hv);
            }
            __syncwarp();
            if (lane == 0) {
                int old;
                asm volatile("atom.release.gpu.global.add.s32 %0, [%1], %2;"
                             : "=r"(old)
                             : "l"(ctr + (size_t)s * STEP_INTS + mygrp * GSTRIDE), "r"(1)
                             : "memory");
            }
        }
    }
}

// ------------------------ emissions: e[L,24] = x2 @ w_out^T + b_out ------------------------
__global__ __launch_bounds__(256) void emis_kernel(
    const float* __restrict__ w_out, const float* __restrict__ b_out)
{
    int tid = threadIdx.x, lane = tid & 31, w = tid >> 5;
    int t = blockIdx.x * 8 + w;
    const float4* xp = (const float4*)(g_x2 + (size_t)t * XW);
    float4 xr[8];
#pragma unroll
    for (int q = 0; q < 8; q++) xr[q] = xp[lane + q * 32];
    for (int j = 0; j < TT; j++) {
        const float4* wp = (const float4*)(w_out + (size_t)j * XW);
        float acc = 0.0f;
#pragma unroll
        for (int q = 0; q < 8; q++) {
            float4 wv = wp[lane + q * 32];
            acc += xr[q].x * wv.x + xr[q].y * wv.y + xr[q].z * wv.z + xr[q].w * wv.w;
        }
        acc = warp_sum(acc);
        if (lane == 0) g_emis[(size_t)t * TT + j] = acc + b_out[j];
    }
}

// ------------------------ CRF NLL ------------------------
__global__ __launch_bounds__(768) void crf_kernel(
    const float* __restrict__ start_trans, const float* __restrict__ end_trans,
    const float* __restrict__ trans, const int* __restrict__ tags,
    float* __restrict__ outp)
{
    __shared__ float trans_sh[TT * 25];
    __shared__ float alpha[2][TT];
    __shared__ float red[24];
    __shared__ float num_sh;

    int tid = threadIdx.x, lane = tid & 31, w = tid >> 5;

    // numerator (parallel part)
    float p = 0.0f;
    for (int t = tid; t < L; t += 768) p += g_emis[(size_t)t * TT + tags[t]];
    for (int t = tid; t < L - 1; t += 768) p += trans[tags[t] * TT + tags[t + 1]];
    p = warp_sum(p);
    if (lane == 0) red[w] = p;

    for (int i = tid; i < TT * TT; i += 768)
        trans_sh[(i / TT) * 25 + (i % TT)] = trans[i];
    if (tid < TT) alpha[0][tid] = start_trans[tid] + g_emis[tid];
    __syncthreads();

    if (w == 0) {
        float q = (lane < 24) ? red[lane] : 0.0f;
        q = warp_sum(q);
        if (lane == 0) num_sh = q + start_trans[tags[0]] + end_trans[tags[L - 1]];
    }
    __syncthreads();

    // forward scan: warp j computes alpha'[j] = logsumexp_i(alpha[i] + trans[i][j]) + e[t][j]
    for (int t = 1; t < L; t++) {
        int cur = t & 1, prv = cur ^ 1;
        if (w < TT) {
            float v = (lane < TT) ? alpha[prv][lane] + trans_sh[lane * 25 + w] : -1e30f;
            float m = warp_max_all(v);
            float e = (lane < TT) ? __expf(v - m) : 0.0f;
            float ssum = warp_sum(e);
            if (lane == 0) alpha[cur][w] = m + logf(ssum) + g_emis[(size_t)t * TT + w];
        }
        __syncthreads();
    }

    if (tid < 32) {
        int tl = (L - 1) & 1;
        float v = (lane < TT) ? alpha[tl][lane] + end_trans[lane] : -1e30f;
        float m = warp_max_all(v);
        float e = (lane < TT) ? __expf(v - m) : 0.0f;
        float ssum = warp_sum(e);
        if (lane == 0) outp[0] = (m + logf(ssum)) - num_sh;
    }
}

// ------------------------ launch ------------------------
extern "C" void kernel_launch(void* const* d_in, const int* in_sizes, int n_in,
                              void* d_out, int out_size)
{
    const float* emb       = (const float*)d_in[0];
    const float* w_ih_l0f  = (const float*)d_in[1];
    const float* w_hh_l0f  = (const float*)d_in[2];
    const float* b_l0f     = (const float*)d_in[3];
    const float* w_ih_l0b  = (const float*)d_in[4];
    const float* w_hh_l0b  = (const float*)d_in[5];
    const float* b_l0b     = (const float*)d_in[6];
    const float* w_ih_l1f  = (const float*)d_in[7];
    const float* w_hh_l1f  = (const float*)d_in[8];
    const float* b_l1f     = (const float*)d_in[9];
    const float* w_ih_l1b  = (const float*)d_in[10];
    const float* w_hh_l1b  = (const float*)d_in[11];
    const float* b_l1b     = (const float*)d_in[12];
    const float* w_out     = (const float*)d_in[13];
    const float* b_out     = (const float*)d_in[14];
    const float* start_tr  = (const float*)d_in[15];
    const float* end_tr    = (const float*)d_in[16];
    const float* trans     = (const float*)d_in[17];
    const int*   sentence  = (const int*)d_in[18];
    const int*   tags      = (const int*)d_in[19];
    float* outp = (float*)d_out;

    float *pre0f, *pre0b, *pre1f, *pre1b, *x1, *x2;
    int* bar;
    cudaGetSymbolAddress((void**)&pre0f, g_pre0f);
    cudaGetSymbolAddress((void**)&pre0b, g_pre0b);
    cudaGetSymbolAddress((void**)&pre1f, g_pre1f);
    cudaGetSymbolAddress((void**)&pre1b, g_pre1b);
    cudaGetSymbolAddress((void**)&x1, g_x1);
    cudaGetSymbolAddress((void**)&x2, g_x2);
    cudaGetSymbolAddress((void**)&bar, g_bar);

    cudaMemsetAsync(bar, 0, (size_t)2 * 2 * L * STEP_INTS * sizeof(int));

    dim3 ggrid(G / 128, L / 128, 2);  // (16, 32, 2)

    // layer 0 input pre-activations (with embedding gather), both directions
    gemm_bias2_kernel<<<ggrid, 256>>>(emb, sentence,
                                      w_ih_l0f, b_l0f, pre0f,
                                      w_ih_l0b, b_l0b, pre0b, L, G, E);

    // layer 0 recurrence -> x1 = concat(hf, hb)
    lstm_kernel<<<2 * RB, RTH>>>(pre0f, pre0b, w_hh_l0f, w_hh_l0b, x1, bar);

    // layer 1 input pre-activations
    gemm_bias2_kernel<<<ggrid, 256>>>(x1, nullptr,
                                      w_ih_l1f, b_l1f, pre1f,
                                      w_ih_l1b, b_l1b, pre1b, L, G, XW);

    // layer 1 recurrence -> x2
    lstm_kernel<<<2 * RB, RTH>>>(pre1f, pre1b, w_hh_l1f, w_hh_l1b, x2,
                                 bar + (size_t)2 * L * STEP_INTS);

    // emissions + CRF
    emis_kernel<<<L / 8, 256>>>(w_out, b_out);
    crf_kernel<<<1, 768>>>(start_tr, end_tr, trans, tags, outp);
}